// round 8
// baseline (speedup 1.0000x reference)
#include <cuda_runtime.h>
#include <cuda_bf16.h>
#include <cstdint>

#define NB 4
#define NC 256
#define NPIX 4096
#define ND 32

// ---------------- device scratch ----------------
__device__ __align__(256) __nv_bfloat16 g_q[(size_t)NB * NPIX * ND];   // [b][n][d]
__device__ __align__(256) __nv_bfloat16 g_k[(size_t)NB * NPIX * ND];   // [b][n][d]
__device__ __align__(256) __nv_bfloat16 g_v[(size_t)NB * NPIX * NC];   // [b][n][c]
__device__ __align__(256) __nv_bfloat16 g_xbf[(size_t)NB * NC * NPIX]; // [b][c][n]
__device__ __align__(256) __nv_bfloat16 g_wall[320 * NC];
__device__ __align__(256) float         g_ball[320];

// ---------------- PTX helpers ----------------
__device__ __forceinline__ uint32_t smem_u32(const void* p) {
    uint32_t a;
    asm("{ .reg .u64 t; cvta.to.shared.u64 t, %1; cvt.u32.u64 %0, t; }" : "=r"(a) : "l"(p));
    return a;
}
__device__ __forceinline__ void cp16(uint32_t dst, const void* src) {
    asm volatile("cp.async.cg.shared.global [%0], [%1], 16;" :: "r"(dst), "l"(src));
}
#define CP_COMMIT() asm volatile("cp.async.commit_group;" ::: "memory")
#define CP_WAIT1()  asm volatile("cp.async.wait_group 1;" ::: "memory")
#define CP_WAIT0()  asm volatile("cp.async.wait_group 0;" ::: "memory")

__device__ __forceinline__ void ldsm4(uint32_t r[4], uint32_t addr) {
    asm volatile("ldmatrix.sync.aligned.m8n8.x4.shared.b16 {%0,%1,%2,%3}, [%4];"
        : "=r"(r[0]), "=r"(r[1]), "=r"(r[2]), "=r"(r[3]) : "r"(addr));
}
__device__ __forceinline__ void ldsm4t(uint32_t r[4], uint32_t addr) {
    asm volatile("ldmatrix.sync.aligned.m8n8.x4.trans.shared.b16 {%0,%1,%2,%3}, [%4];"
        : "=r"(r[0]), "=r"(r[1]), "=r"(r[2]), "=r"(r[3]) : "r"(addr));
}
__device__ __forceinline__ void mma16816(float c[4], const uint32_t a[4],
                                         uint32_t b0, uint32_t b1) {
    asm volatile(
        "mma.sync.aligned.m16n8k16.row.col.f32.bf16.bf16.f32 "
        "{%0,%1,%2,%3}, {%4,%5,%6,%7}, {%8,%9}, {%0,%1,%2,%3};"
        : "+f"(c[0]), "+f"(c[1]), "+f"(c[2]), "+f"(c[3])
        : "r"(a[0]), "r"(a[1]), "r"(a[2]), "r"(a[3]), "r"(b0), "r"(b1));
}
__device__ __forceinline__ uint32_t packbf(float lo, float hi) {
    uint32_t r;
    asm("cvt.rn.satfinite.bf16x2.f32 %0, %1, %2;" : "=r"(r) : "f"(hi), "f"(lo));
    return r;
}
__device__ __forceinline__ void sts32(uint32_t addr, uint32_t v) {
    asm volatile("st.shared.b32 [%0], %1;" :: "r"(addr), "r"(v) : "memory");
}

// ---------------- kernel 0a: x -> bf16 ----------------
__global__ void __launch_bounds__(256)
xconvert(const float* __restrict__ x, __nv_bfloat16* __restrict__ xbf)
{
    size_t i4 = (size_t)blockIdx.x * 256 + threadIdx.x;
    float4 v = reinterpret_cast<const float4*>(x)[i4];
    uint2 o;
    o.x = packbf(v.x, v.y);
    o.y = packbf(v.z, v.w);
    reinterpret_cast<uint2*>(xbf)[i4] = o;
}

// ---------------- kernel 0b: pack Wq/Wk/Wv + biases ----------------
__global__ void __launch_bounds__(256)
packw(const float* __restrict__ Wq, const float* __restrict__ bq,
      const float* __restrict__ Wk, const float* __restrict__ bk,
      const float* __restrict__ Wv, const float* __restrict__ bv,
      __nv_bfloat16* __restrict__ wall, float* __restrict__ ball)
{
    int r = blockIdx.x;
    int c = threadIdx.x;
    float wv, bvl;
    if (r < 32)       { wv = Wq[(size_t)r * NC + c];        bvl = bq[r]; }
    else if (r < 64)  { wv = Wk[(size_t)(r - 32) * NC + c]; bvl = bk[r - 32]; }
    else              { wv = Wv[(size_t)(r - 64) * NC + c]; bvl = bv[r - 64]; }
    wall[(size_t)r * NC + c] = __float2bfloat16(wv);
    if (c == 0) ball[r] = bvl;
}

// ---------------- kernel 1: fused HMMA projection (unchanged) ----------------
#define XSTR 144
#define WSTR 528
#define PSM_X 0
#define PSM_W (256 * XSTR)
#define PSM_TOTAL (PSM_W + 320 * WSTR)

__global__ void __launch_bounds__(256, 1)
proj_fused(const __nv_bfloat16* __restrict__ xbf,
           const __nv_bfloat16* __restrict__ wall,
           const float* __restrict__ ball,
           __nv_bfloat16* __restrict__ q,
           __nv_bfloat16* __restrict__ k,
           __nv_bfloat16* __restrict__ v)
{
    extern __shared__ char smem[];
    const uint32_t sb = smem_u32(smem);
    const int b   = blockIdx.y;
    const int n0  = blockIdx.x * 64;
    const int tid = threadIdx.x;
    const int w = tid >> 5, lane = tid & 31;
    const int m0  = (w >> 1) * 16;
    const int ncb = (w & 1) * 160;
    const int grp = lane >> 3, rr = lane & 7;
    const int gr = lane >> 2, lc = lane & 3;

    #pragma unroll
    for (int it = 0; it < 8; ++it) {
        int idx = tid + it * 256;
        int r = idx >> 3, c = idx & 7;
        cp16(sb + PSM_X + (uint32_t)r * XSTR + c * 16,
             xbf + ((size_t)b * NC + r) * NPIX + n0 + c * 8);
    }
    #pragma unroll
    for (int it = 0; it < 40; ++it) {
        int idx = tid + it * 256;
        int r = idx >> 5, c = idx & 31;
        cp16(sb + PSM_W + (uint32_t)r * WSTR + c * 16,
             wall + (size_t)r * NC + c * 8);
    }
    CP_COMMIT();
    CP_WAIT0();
    __syncthreads();

    float acc[20][4];
    #pragma unroll
    for (int j = 0; j < 20; ++j)
        #pragma unroll
        for (int i = 0; i < 4; ++i) acc[j][i] = 0.f;

    #pragma unroll 4
    for (int ks = 0; ks < 16; ++ks) {
        uint32_t af[4];
        ldsm4t(af, sb + PSM_X
                   + (uint32_t)(ks * 16 + (grp >> 1) * 8 + rr) * XSTR
                   + (m0 + (grp & 1) * 8) * 2);
        #pragma unroll
        for (int j = 0; j < 10; ++j) {
            uint32_t bfr[4];
            ldsm4(bfr, sb + PSM_W
                       + (uint32_t)(ncb + j * 16 + (grp >> 1) * 8 + rr) * WSTR
                       + ks * 32 + (grp & 1) * 16);
            mma16816(acc[2 * j],     af, bfr[0], bfr[1]);
            mma16816(acc[2 * j + 1], af, bfr[2], bfr[3]);
        }
    }

    const int row0 = n0 + m0 + gr;
    #pragma unroll
    for (int j = 0; j < 20; ++j) {
        int col = ncb + j * 8 + 2 * lc;
        float b0 = ball[col], b1 = ball[col + 1];
        uint32_t lop = packbf(acc[j][0] + b0, acc[j][1] + b1);
        uint32_t hip = packbf(acc[j][2] + b0, acc[j][3] + b1);
        uint32_t* dst;
        int cc;
        if (col < 32)      { dst = reinterpret_cast<uint32_t*>(q); cc = col;
                             size_t r0 = ((size_t)b * NPIX + row0) * ND + cc;
                             dst[r0 >> 1] = lop;
                             dst[(r0 + 8 * ND) >> 1] = hip; }
        else if (col < 64) { dst = reinterpret_cast<uint32_t*>(k); cc = col - 32;
                             size_t r0 = ((size_t)b * NPIX + row0) * ND + cc;
                             dst[r0 >> 1] = lop;
                             dst[(r0 + 8 * ND) >> 1] = hip; }
        else               { dst = reinterpret_cast<uint32_t*>(v); cc = col - 64;
                             size_t r0 = ((size_t)b * NPIX + row0) * NC + cc;
                             dst[r0 >> 1] = lop;
                             dst[(r0 + 8 * NC) >> 1] = hip; }
    }
}

// ---------------- kernel 2: HMMA flash attention, P shared via smem ----------------
// CTA: 64 queries, 256 threads = 8 warps: qb = w>>1 (16 rows), ch = w&1.
// QK split by key-half (kh = ch): each warp computes S/exp for 32 keys only,
// stores P(bf16) to smem; PV reloads full-key P via ldmatrix. 2 CTAs/SM.
#define KSTRIDE 80
#define VSTRIDE 528
#define PSTRIDE 272       // 128B P row + 16B pad (272 = 68 words = 4 mod 32: conflict-free)
#define SQ  0
#define SK0 (SQ  + 64 * KSTRIDE)
#define SK1 (SK0 + 64 * KSTRIDE)
#define SV0 (SK1 + 64 * KSTRIDE)
#define SV1 (SV0 + 64 * VSTRIDE)
#define SP  (SV1 + 64 * VSTRIDE)
#define SL  (SP  + 64 * PSTRIDE)
#define SM_TOTAL (SL + 2 * 64 * 4)     // 100,864 + 512 = 101,376 bytes (<113K: 2 CTAs/SM)

__global__ void __launch_bounds__(256, 2)
attn_kernel(const float* __restrict__ x, const float* __restrict__ gamma,
            float* __restrict__ out)
{
    extern __shared__ char smem[];
    const uint32_t sb = smem_u32(smem);
    const int b   = blockIdx.y;
    const int n0q = blockIdx.x * 64;
    const int tid = threadIdx.x;
    const int w = tid >> 5, lane = tid & 31;
    const int qb = w >> 1;          // query block (16 rows)
    const int ch = w & 1;           // channel half / key half
    const int grp = lane >> 3, rr = lane & 7;
    const int gr = lane >> 2, lc = lane & 3;

    const __nv_bfloat16* qg = g_q + ((size_t)b * NPIX + n0q) * ND;
    const __nv_bfloat16* kg = g_k + (size_t)b * NPIX * ND;
    const __nv_bfloat16* vg = g_v + (size_t)b * NPIX * NC;

    // ---- prologue: Q + K0 + V0 ----
    {
        int r = tid >> 2, c = tid & 3;
        cp16(sb + SQ + (uint32_t)r * KSTRIDE + c * 16, qg + (size_t)r * ND + c * 8);
        cp16(sb + SK0 + (uint32_t)r * KSTRIDE + c * 16, kg + (size_t)r * ND + c * 8);
    }
    #pragma unroll
    for (int it = 0; it < 8; ++it) {
        int idx = tid + it * 256;
        int r = idx >> 5, c = idx & 31;
        cp16(sb + SV0 + (uint32_t)r * VSTRIDE + c * 16, vg + (size_t)r * NC + c * 8);
    }
    CP_COMMIT();

    float Oacc[16][4];
    #pragma unroll
    for (int i = 0; i < 16; ++i)
        #pragma unroll
        for (int j = 0; j < 4; ++j) Oacc[i][j] = 0.f;
    float l_lo = 0.f, l_hi = 0.f;
    uint32_t qf[2][4];

    for (int t = 0; t < 64; ++t) {
        __syncthreads();   // previous compute (incl. PV reads of P & V) done
        const uint32_t kbuf = sb + ((t & 1) ? SK1 : SK0);
        const uint32_t vbuf = sb + ((t & 1) ? SV1 : SV0);
        if (t < 63) {
            const uint32_t kbufN = sb + ((t & 1) ? SK0 : SK1);
            const uint32_t vbufN = sb + ((t & 1) ? SV0 : SV1);
            const int k0n = (t + 1) * 64;
            {
                int r = tid >> 2, c = tid & 3;
                cp16(kbufN + (uint32_t)r * KSTRIDE + c * 16,
                     kg + (size_t)(k0n + r) * ND + c * 8);
            }
            #pragma unroll
            for (int it = 0; it < 8; ++it) {
                int idx = tid + it * 256;
                int r = idx >> 5, c = idx & 31;
                cp16(vbufN + (uint32_t)r * VSTRIDE + c * 16,
                     vg + (size_t)(k0n + r) * NC + c * 8);
            }
            CP_COMMIT();
            CP_WAIT1();
        } else {
            CP_WAIT0();
        }
        __syncthreads();   // tile t visible

        if (t == 0) {      // Q A-fragments (once)
            #pragma unroll
            for (int ks = 0; ks < 2; ++ks) {
                uint32_t addr = sb + SQ
                    + (uint32_t)(qb * 16 + (grp & 1) * 8 + rr) * KSTRIDE
                    + ks * 32 + (grp >> 1) * 16;
                ldsm4(qf[ks], addr);
            }
        }

        // ---- S = Q * K^T for this warp's 32-key half (kh = ch) ----
        float sacc[4][4];
        #pragma unroll
        for (int i = 0; i < 4; ++i)
            #pragma unroll
            for (int j = 0; j < 4; ++j) sacc[i][j] = 0.f;
        #pragma unroll
        for (int ks = 0; ks < 2; ++ks) {
            #pragma unroll
            for (int p = 0; p < 2; ++p) {
                uint32_t bfr[4];
                uint32_t addr = kbuf
                    + (uint32_t)(ch * 32 + p * 16 + (grp >> 1) * 8 + rr) * KSTRIDE
                    + ks * 32 + (grp & 1) * 16;
                ldsm4(bfr, addr);
                mma16816(sacc[2 * p],     qf[ks], bfr[0], bfr[1]);
                mma16816(sacc[2 * p + 1], qf[ks], bfr[2], bfr[3]);
            }
        }

        // ---- exp (16 values/thread), store P to smem ----
        #pragma unroll
        for (int nt = 0; nt < 4; ++nt) {
            float e0 = __expf(sacc[nt][0]);
            float e1 = __expf(sacc[nt][1]);
            float e2 = __expf(sacc[nt][2]);
            float e3 = __expf(sacc[nt][3]);
            l_lo += e0 + e1;
            l_hi += e2 + e3;
            uint32_t jb = (uint32_t)(ch * 32 + nt * 8 + 2 * lc) * 2;   // key byte offset
            sts32(sb + SP + (uint32_t)(qb * 16 + gr)     * PSTRIDE + jb, packbf(e0, e1));
            sts32(sb + SP + (uint32_t)(qb * 16 + gr + 8) * PSTRIDE + jb, packbf(e2, e3));
        }
        __syncthreads();   // P complete (both key halves)

        // ---- O += P * V : 16 n8-tiles (128 chans), 4 k16 steps ----
        #pragma unroll
        for (int kb = 0; kb < 4; ++kb) {
            uint32_t pf[4];
            ldsm4(pf, sb + SP
                      + (uint32_t)(qb * 16 + (grp & 1) * 8 + rr) * PSTRIDE
                      + kb * 32 + (grp >> 1) * 16);
            #pragma unroll
            for (int np = 0; np < 8; ++np) {
                uint32_t bfr[4];
                uint32_t addr = vbuf
                    + (uint32_t)(kb * 16 + (grp & 1) * 8 + rr) * VSTRIDE
                    + ch * 256 + np * 32 + (grp >> 1) * 16;
                ldsm4t(bfr, addr);
                mma16816(Oacc[2 * np],     pf, bfr[0], bfr[1]);
                mma16816(Oacc[2 * np + 1], pf, bfr[2], bfr[3]);
            }
        }
    }

    // ---- l: quad-reduce (over lc), publish per key-half, combine ----
    l_lo += __shfl_xor_sync(0xFFFFFFFF, l_lo, 1);
    l_lo += __shfl_xor_sync(0xFFFFFFFF, l_lo, 2);
    l_hi += __shfl_xor_sync(0xFFFFFFFF, l_hi, 1);
    l_hi += __shfl_xor_sync(0xFFFFFFFF, l_hi, 2);
    float* L = (float*)(smem + SL);           // [kh][64 rows]
    if (lc == 0) {
        L[ch * 64 + qb * 16 + gr]     = l_lo;
        L[ch * 64 + qb * 16 + gr + 8] = l_hi;
    }
    __syncthreads();
    const float gma = gamma[0];
    const float inv_lo = gma / (L[qb * 16 + gr]     + L[64 + qb * 16 + gr]);
    const float inv_hi = gma / (L[qb * 16 + gr + 8] + L[64 + qb * 16 + gr + 8]);

    // ---- epilogue ----
    const int pix0 = n0q + qb * 16 + gr;
    #pragma unroll
    for (int nt = 0; nt < 16; ++nt) {
        int c0 = ch * 128 + nt * 8 + 2 * lc;
        size_t i00 = ((size_t)b * NC + c0) * NPIX + pix0;
        size_t i01 = i00 + NPIX;
        out[i00] = Oacc[nt][0] * inv_lo + x[i00];
        out[i01] = Oacc[nt][1] * inv_lo + x[i01];
        size_t i10 = i00 + 8;
        size_t i11 = i01 + 8;
        out[i10] = Oacc[nt][2] * inv_hi + x[i10];
        out[i11] = Oacc[nt][3] * inv_hi + x[i11];
    }
}

// ---------------- launch ----------------
extern "C" void kernel_launch(void* const* d_in, const int* in_sizes, int n_in,
                              void* d_out, int out_size)
{
    (void)in_sizes; (void)n_in; (void)out_size;
    const float* x     = (const float*)d_in[0];
    const float* Wq    = (const float*)d_in[1];
    const float* bq    = (const float*)d_in[2];
    const float* Wk    = (const float*)d_in[3];
    const float* bk    = (const float*)d_in[4];
    const float* Wv    = (const float*)d_in[5];
    const float* bv    = (const float*)d_in[6];
    const float* gamma = (const float*)d_in[7];
    float* out = (float*)d_out;

    void* p;
    cudaGetSymbolAddress(&p, g_q);    __nv_bfloat16* qT  = (__nv_bfloat16*)p;
    cudaGetSymbolAddress(&p, g_k);    __nv_bfloat16* kT  = (__nv_bfloat16*)p;
    cudaGetSymbolAddress(&p, g_v);    __nv_bfloat16* vT  = (__nv_bfloat16*)p;
    cudaGetSymbolAddress(&p, g_xbf);  __nv_bfloat16* xbf = (__nv_bfloat16*)p;
    cudaGetSymbolAddress(&p, g_wall); __nv_bfloat16* wal = (__nv_bfloat16*)p;
    cudaGetSymbolAddress(&p, g_ball); float*         bal = (float*)p;

    static int attr_set = 0;
    if (!attr_set) {
        cudaFuncSetAttribute(attn_kernel,
                             cudaFuncAttributeMaxDynamicSharedMemorySize, SM_TOTAL);
        cudaFuncSetAttribute(proj_fused,
                             cudaFuncAttributeMaxDynamicSharedMemorySize, PSM_TOTAL);
        attr_set = 1;
    }

    xconvert<<<(NB * NC * NPIX) / (256 * 4), 256>>>(x, xbf);
    packw<<<320, 256>>>(Wq, bq, Wk, bk, Wv, bv, wal, bal);
    proj_fused<<<dim3(NPIX / 64, NB), 256, PSM_TOTAL>>>(xbf, wal, bal, qT, kT, vT);
    attn_kernel<<<dim3(NPIX / 64, NB), 256, SM_TOTAL>>>(x, gamma, out);
}

// round 9
// speedup vs baseline: 1.4492x; 1.4492x over previous
#include <cuda_runtime.h>
#include <cuda_bf16.h>
#include <cstdint>

#define NB 4
#define NC 256
#define NPIX 4096
#define ND 32

// ---------------- device scratch ----------------
__device__ __align__(256) __nv_bfloat16 g_q[(size_t)NB * NPIX * ND];   // [b][n][d] (pre-scaled by log2e)
__device__ __align__(256) __nv_bfloat16 g_k[(size_t)NB * NPIX * ND];   // [b][n][d]
__device__ __align__(256) __nv_bfloat16 g_v[(size_t)NB * NPIX * NC];   // [b][n][c]
__device__ __align__(256) __nv_bfloat16 g_xbf[(size_t)NB * NC * NPIX]; // [b][c][n]
__device__ __align__(256) __nv_bfloat16 g_wall[320 * NC];
__device__ __align__(256) float         g_ball[320];

// ---------------- PTX helpers ----------------
__device__ __forceinline__ uint32_t smem_u32(const void* p) {
    uint32_t a;
    asm("{ .reg .u64 t; cvta.to.shared.u64 t, %1; cvt.u32.u64 %0, t; }" : "=r"(a) : "l"(p));
    return a;
}
__device__ __forceinline__ void cp16(uint32_t dst, const void* src) {
    asm volatile("cp.async.cg.shared.global [%0], [%1], 16;" :: "r"(dst), "l"(src));
}
#define CP_COMMIT() asm volatile("cp.async.commit_group;" ::: "memory")
#define CP_WAIT1()  asm volatile("cp.async.wait_group 1;" ::: "memory")
#define CP_WAIT0()  asm volatile("cp.async.wait_group 0;" ::: "memory")

__device__ __forceinline__ void ldsm4(uint32_t r[4], uint32_t addr) {
    asm volatile("ldmatrix.sync.aligned.m8n8.x4.shared.b16 {%0,%1,%2,%3}, [%4];"
        : "=r"(r[0]), "=r"(r[1]), "=r"(r[2]), "=r"(r[3]) : "r"(addr));
}
__device__ __forceinline__ void ldsm4t(uint32_t r[4], uint32_t addr) {
    asm volatile("ldmatrix.sync.aligned.m8n8.x4.trans.shared.b16 {%0,%1,%2,%3}, [%4];"
        : "=r"(r[0]), "=r"(r[1]), "=r"(r[2]), "=r"(r[3]) : "r"(addr));
}
__device__ __forceinline__ void mma16816(float c[4], const uint32_t a[4],
                                         uint32_t b0, uint32_t b1) {
    asm volatile(
        "mma.sync.aligned.m16n8k16.row.col.f32.bf16.bf16.f32 "
        "{%0,%1,%2,%3}, {%4,%5,%6,%7}, {%8,%9}, {%0,%1,%2,%3};"
        : "+f"(c[0]), "+f"(c[1]), "+f"(c[2]), "+f"(c[3])
        : "r"(a[0]), "r"(a[1]), "r"(a[2]), "r"(a[3]), "r"(b0), "r"(b1));
}
__device__ __forceinline__ uint32_t packbf(float lo, float hi) {
    uint32_t r;
    asm("cvt.rn.satfinite.bf16x2.f32 %0, %1, %2;" : "=r"(r) : "f"(hi), "f"(lo));
    return r;
}
__device__ __forceinline__ float ex2f(float x) {
    float y;
    asm("ex2.approx.f32 %0, %1;" : "=f"(y) : "f"(x));
    return y;
}

// ---------------- kernel 0a: x -> bf16 ----------------
__global__ void __launch_bounds__(256)
xconvert(const float* __restrict__ x, __nv_bfloat16* __restrict__ xbf)
{
    size_t i4 = (size_t)blockIdx.x * 256 + threadIdx.x;
    float4 v = reinterpret_cast<const float4*>(x)[i4];
    uint2 o;
    o.x = packbf(v.x, v.y);
    o.y = packbf(v.z, v.w);
    reinterpret_cast<uint2*>(xbf)[i4] = o;
}

// ---------------- kernel 0b: pack Wq/Wk/Wv + biases (Wq,bq scaled by log2e) ----------------
__global__ void __launch_bounds__(256)
packw(const float* __restrict__ Wq, const float* __restrict__ bq,
      const float* __restrict__ Wk, const float* __restrict__ bk,
      const float* __restrict__ Wv, const float* __restrict__ bv,
      __nv_bfloat16* __restrict__ wall, float* __restrict__ ball)
{
    const float LOG2E = 1.4426950408889634f;
    int r = blockIdx.x;
    int c = threadIdx.x;
    float wv, bvl;
    if (r < 32)       { wv = Wq[(size_t)r * NC + c] * LOG2E;  bvl = bq[r] * LOG2E; }
    else if (r < 64)  { wv = Wk[(size_t)(r - 32) * NC + c];   bvl = bk[r - 32]; }
    else              { wv = Wv[(size_t)(r - 64) * NC + c];   bvl = bv[r - 64]; }
    wall[(size_t)r * NC + c] = __float2bfloat16(wv);
    if (c == 0) ball[r] = bvl;
}

// ---------------- kernel 1: fused HMMA projection (unchanged) ----------------
#define XSTR 144
#define WSTR 528
#define PSM_X 0
#define PSM_W (256 * XSTR)
#define PSM_TOTAL (PSM_W + 320 * WSTR)

__global__ void __launch_bounds__(256, 1)
proj_fused(const __nv_bfloat16* __restrict__ xbf,
           const __nv_bfloat16* __restrict__ wall,
           const float* __restrict__ ball,
           __nv_bfloat16* __restrict__ q,
           __nv_bfloat16* __restrict__ k,
           __nv_bfloat16* __restrict__ v)
{
    extern __shared__ char smem[];
    const uint32_t sb = smem_u32(smem);
    const int b   = blockIdx.y;
    const int n0  = blockIdx.x * 64;
    const int tid = threadIdx.x;
    const int w = tid >> 5, lane = tid & 31;
    const int m0  = (w >> 1) * 16;
    const int ncb = (w & 1) * 160;
    const int grp = lane >> 3, rr = lane & 7;
    const int gr = lane >> 2, lc = lane & 3;

    #pragma unroll
    for (int it = 0; it < 8; ++it) {
        int idx = tid + it * 256;
        int r = idx >> 3, c = idx & 7;
        cp16(sb + PSM_X + (uint32_t)r * XSTR + c * 16,
             xbf + ((size_t)b * NC + r) * NPIX + n0 + c * 8);
    }
    #pragma unroll
    for (int it = 0; it < 40; ++it) {
        int idx = tid + it * 256;
        int r = idx >> 5, c = idx & 31;
        cp16(sb + PSM_W + (uint32_t)r * WSTR + c * 16,
             wall + (size_t)r * NC + c * 8);
    }
    CP_COMMIT();
    CP_WAIT0();
    __syncthreads();

    float acc[20][4];
    #pragma unroll
    for (int j = 0; j < 20; ++j)
        #pragma unroll
        for (int i = 0; i < 4; ++i) acc[j][i] = 0.f;

    #pragma unroll 4
    for (int ks = 0; ks < 16; ++ks) {
        uint32_t af[4];
        ldsm4t(af, sb + PSM_X
                   + (uint32_t)(ks * 16 + (grp >> 1) * 8 + rr) * XSTR
                   + (m0 + (grp & 1) * 8) * 2);
        #pragma unroll
        for (int j = 0; j < 10; ++j) {
            uint32_t bfr[4];
            ldsm4(bfr, sb + PSM_W
                       + (uint32_t)(ncb + j * 16 + (grp >> 1) * 8 + rr) * WSTR
                       + ks * 32 + (grp & 1) * 16);
            mma16816(acc[2 * j],     af, bfr[0], bfr[1]);
            mma16816(acc[2 * j + 1], af, bfr[2], bfr[3]);
        }
    }

    const int row0 = n0 + m0 + gr;
    #pragma unroll
    for (int j = 0; j < 20; ++j) {
        int col = ncb + j * 8 + 2 * lc;
        float b0 = ball[col], b1 = ball[col + 1];
        uint32_t lop = packbf(acc[j][0] + b0, acc[j][1] + b1);
        uint32_t hip = packbf(acc[j][2] + b0, acc[j][3] + b1);
        uint32_t* dst;
        int cc;
        if (col < 32)      { dst = reinterpret_cast<uint32_t*>(q); cc = col;
                             size_t r0 = ((size_t)b * NPIX + row0) * ND + cc;
                             dst[r0 >> 1] = lop;
                             dst[(r0 + 8 * ND) >> 1] = hip; }
        else if (col < 64) { dst = reinterpret_cast<uint32_t*>(k); cc = col - 32;
                             size_t r0 = ((size_t)b * NPIX + row0) * ND + cc;
                             dst[r0 >> 1] = lop;
                             dst[(r0 + 8 * ND) >> 1] = hip; }
        else               { dst = reinterpret_cast<uint32_t*>(v); cc = col - 64;
                             size_t r0 = ((size_t)b * NPIX + row0) * NC + cc;
                             dst[r0 >> 1] = lop;
                             dst[(r0 + 8 * NC) >> 1] = hip; }
    }
}

// ---------------- kernel 2: HMMA flash attention (R4 dataflow, 128-key tiles) ----------------
// CTA: 64 queries, 256 threads = 8 warps: qb = w>>1 (16 rows), ch = w&1 (128 chans).
// Outer tile = 128 keys (double-buffered), processed as two 64-key halves with
// the R4 register footprint. exp = bare ex2 (q pre-scaled by log2e).
#define KSTRIDE 80
#define VSTRIDE 528
#define SQ  0
#define SK0 (SQ  + 64 * KSTRIDE)                 // K bufs: 128 rows each
#define SK1 (SK0 + 128 * KSTRIDE)
#define SV0 (SK1 + 128 * KSTRIDE)                // V bufs: 128 rows each
#define SV1 (SV0 + 128 * VSTRIDE)
#define SM_TOTAL (SV1 + 128 * VSTRIDE)           // 160,768 bytes

__global__ void __launch_bounds__(256, 1)
attn_kernel(const float* __restrict__ x, const float* __restrict__ gamma,
            float* __restrict__ out)
{
    extern __shared__ char smem[];
    const uint32_t sb = smem_u32(smem);
    const int b   = blockIdx.y;
    const int n0q = blockIdx.x * 64;
    const int tid = threadIdx.x;
    const int w = tid >> 5, lane = tid & 31;
    const int qb = w >> 1;
    const int ch = w & 1;
    const int grp = lane >> 3, rr = lane & 7;
    const int gr = lane >> 2, lc = lane & 3;

    const __nv_bfloat16* qg = g_q + ((size_t)b * NPIX + n0q) * ND;
    const __nv_bfloat16* kg = g_k + (size_t)b * NPIX * ND;
    const __nv_bfloat16* vg = g_v + (size_t)b * NPIX * NC;

    // ---- prologue: Q + tile 0 (128 keys) ----
    {
        int r = tid >> 2, c = tid & 3;
        cp16(sb + SQ + (uint32_t)r * KSTRIDE + c * 16, qg + (size_t)r * ND + c * 8);
    }
    #pragma unroll
    for (int it = 0; it < 2; ++it) {          // K: 128 rows x 4 cp16
        int idx = tid + it * 256;
        int r = idx >> 2, c = idx & 3;
        cp16(sb + SK0 + (uint32_t)r * KSTRIDE + c * 16, kg + (size_t)r * ND + c * 8);
    }
    #pragma unroll
    for (int it = 0; it < 16; ++it) {         // V: 128 rows x 32 cp16
        int idx = tid + it * 256;
        int r = idx >> 5, c = idx & 31;
        cp16(sb + SV0 + (uint32_t)r * VSTRIDE + c * 16, vg + (size_t)r * NC + c * 8);
    }
    CP_COMMIT();

    float Oacc[16][4];
    #pragma unroll
    for (int i = 0; i < 16; ++i)
        #pragma unroll
        for (int j = 0; j < 4; ++j) Oacc[i][j] = 0.f;
    float l_lo = 0.f, l_hi = 0.f;
    uint32_t qf[2][4];

    for (int t = 0; t < 32; ++t) {
        __syncthreads();   // previous compute done before buffer overwrite
        const uint32_t kbuf = sb + ((t & 1) ? SK1 : SK0);
        const uint32_t vbuf = sb + ((t & 1) ? SV1 : SV0);
        if (t < 31) {
            const uint32_t kbufN = sb + ((t & 1) ? SK0 : SK1);
            const uint32_t vbufN = sb + ((t & 1) ? SV0 : SV1);
            const int k0n = (t + 1) * 128;
            #pragma unroll
            for (int it = 0; it < 2; ++it) {
                int idx = tid + it * 256;
                int r = idx >> 2, c = idx & 3;
                cp16(kbufN + (uint32_t)r * KSTRIDE + c * 16,
                     kg + (size_t)(k0n + r) * ND + c * 8);
            }
            #pragma unroll
            for (int it = 0; it < 16; ++it) {
                int idx = tid + it * 256;
                int r = idx >> 5, c = idx & 31;
                cp16(vbufN + (uint32_t)r * VSTRIDE + c * 16,
                     vg + (size_t)(k0n + r) * NC + c * 8);
            }
            CP_COMMIT();
            CP_WAIT1();
        } else {
            CP_WAIT0();
        }
        __syncthreads();   // tile t visible

        if (t == 0) {      // Q A-fragments (once)
            #pragma unroll
            for (int ks = 0; ks < 2; ++ks) {
                uint32_t addr = sb + SQ
                    + (uint32_t)(qb * 16 + (grp & 1) * 8 + rr) * KSTRIDE
                    + ks * 32 + (grp >> 1) * 16;
                ldsm4(qf[ks], addr);
            }
        }

        // ---- two 64-key halves (R4 register footprint) ----
        #pragma unroll
        for (int h = 0; h < 2; ++h) {
            const uint32_t kh = kbuf + (uint32_t)(h * 64) * KSTRIDE;
            const uint32_t vh = vbuf + (uint32_t)(h * 64) * VSTRIDE;

            // S = Q*K^T : 8 n8-tiles, 2 k16 steps
            float sacc[8][4];
            #pragma unroll
            for (int i = 0; i < 8; ++i)
                #pragma unroll
                for (int j = 0; j < 4; ++j) sacc[i][j] = 0.f;
            #pragma unroll
            for (int ks = 0; ks < 2; ++ks) {
                #pragma unroll
                for (int p = 0; p < 4; ++p) {
                    uint32_t bfr[4];
                    uint32_t addr = kh
                        + (uint32_t)(p * 16 + (grp >> 1) * 8 + rr) * KSTRIDE
                        + ks * 32 + (grp & 1) * 16;
                    ldsm4(bfr, addr);
                    mma16816(sacc[2 * p],     qf[ks], bfr[0], bfr[1]);
                    mma16816(sacc[2 * p + 1], qf[ks], bfr[2], bfr[3]);
                }
            }

            // exp (ex2 — q pre-scaled), row-sum, pack P fragments
            uint32_t pf[4][4];
            #pragma unroll
            for (int nt = 0; nt < 8; ++nt) {
                float e0 = ex2f(sacc[nt][0]);
                float e1 = ex2f(sacc[nt][1]);
                float e2 = ex2f(sacc[nt][2]);
                float e3 = ex2f(sacc[nt][3]);
                l_lo += e0 + e1;
                l_hi += e2 + e3;
                int kb = nt >> 1;
                if ((nt & 1) == 0) {
                    pf[kb][0] = packbf(e0, e1);
                    pf[kb][1] = packbf(e2, e3);
                } else {
                    pf[kb][2] = packbf(e0, e1);
                    pf[kb][3] = packbf(e2, e3);
                }
            }

            // O += P*V : 16 n8-tiles (128 chans), 4 k16 steps
            #pragma unroll
            for (int kb = 0; kb < 4; ++kb) {
                #pragma unroll
                for (int np = 0; np < 8; ++np) {
                    uint32_t bfr[4];
                    uint32_t addr = vh
                        + (uint32_t)(kb * 16 + (grp & 1) * 8 + rr) * VSTRIDE
                        + ch * 256 + np * 32 + (grp >> 1) * 16;
                    ldsm4t(bfr, addr);
                    mma16816(Oacc[2 * np],     pf[kb], bfr[0], bfr[1]);
                    mma16816(Oacc[2 * np + 1], pf[kb], bfr[2], bfr[3]);
                }
            }
        }
    }

    // ---- reduce l across the quad ----
    l_lo += __shfl_xor_sync(0xFFFFFFFF, l_lo, 1);
    l_lo += __shfl_xor_sync(0xFFFFFFFF, l_lo, 2);
    l_hi += __shfl_xor_sync(0xFFFFFFFF, l_hi, 1);
    l_hi += __shfl_xor_sync(0xFFFFFFFF, l_hi, 2);
    const float gma = gamma[0];
    const float inv_lo = gma / l_lo;
    const float inv_hi = gma / l_hi;

    // ---- epilogue ----
    const int pix0 = n0q + qb * 16 + gr;
    #pragma unroll
    for (int nt = 0; nt < 16; ++nt) {
        int c0 = ch * 128 + nt * 8 + 2 * lc;
        size_t i00 = ((size_t)b * NC + c0) * NPIX + pix0;
        size_t i01 = i00 + NPIX;
        out[i00] = Oacc[nt][0] * inv_lo + x[i00];
        out[i01] = Oacc[nt][1] * inv_lo + x[i01];
        size_t i10 = i00 + 8;
        size_t i11 = i01 + 8;
        out[i10] = Oacc[nt][2] * inv_hi + x[i10];
        out[i11] = Oacc[nt][3] * inv_hi + x[i11];
    }
}

// ---------------- launch ----------------
extern "C" void kernel_launch(void* const* d_in, const int* in_sizes, int n_in,
                              void* d_out, int out_size)
{
    (void)in_sizes; (void)n_in; (void)out_size;
    const float* x     = (const float*)d_in[0];
    const float* Wq    = (const float*)d_in[1];
    const float* bq    = (const float*)d_in[2];
    const float* Wk    = (const float*)d_in[3];
    const float* bk    = (const float*)d_in[4];
    const float* Wv    = (const float*)d_in[5];
    const float* bv    = (const float*)d_in[6];
    const float* gamma = (const float*)d_in[7];
    float* out = (float*)d_out;

    void* p;
    cudaGetSymbolAddress(&p, g_q);    __nv_bfloat16* qT  = (__nv_bfloat16*)p;
    cudaGetSymbolAddress(&p, g_k);    __nv_bfloat16* kT  = (__nv_bfloat16*)p;
    cudaGetSymbolAddress(&p, g_v);    __nv_bfloat16* vT  = (__nv_bfloat16*)p;
    cudaGetSymbolAddress(&p, g_xbf);  __nv_bfloat16* xbf = (__nv_bfloat16*)p;
    cudaGetSymbolAddress(&p, g_wall); __nv_bfloat16* wal = (__nv_bfloat16*)p;
    cudaGetSymbolAddress(&p, g_ball); float*         bal = (float*)p;

    static int attr_set = 0;
    if (!attr_set) {
        cudaFuncSetAttribute(attn_kernel,
                             cudaFuncAttributeMaxDynamicSharedMemorySize, SM_TOTAL);
        cudaFuncSetAttribute(proj_fused,
                             cudaFuncAttributeMaxDynamicSharedMemorySize, PSM_TOTAL);
        attr_set = 1;
    }

    xconvert<<<(NB * NC * NPIX) / (256 * 4), 256>>>(x, xbf);
    packw<<<320, 256>>>(Wq, bq, Wk, bk, Wv, bv, wal, bal);
    proj_fused<<<dim3(NPIX / 64, NB), 256, PSM_TOTAL>>>(xbf, wal, bal, qT, kT, vT);
    attn_kernel<<<dim3(NPIX / 64, NB), 256, SM_TOTAL>>>(x, gamma, out);
}